// round 3
// baseline (speedup 1.0000x reference)
#include <cuda_runtime.h>
#include <math.h>

// Problem constants
#define BB   32
#define SS   1024
#define ML   500
#define HH   100
#define DDIM 200
#define EMBD 768
#define NROWS (BB*ML)   // 16000

// ---------------- scratch (device globals; no runtime allocation) -------------
__device__ float g_tmps  [NROWS*EMBD];     // seg-summed tokens
__device__ float g_xpf   [NROWS*4*HH];     // LSTM fwd input proj
__device__ float g_xpb   [NROWS*4*HH];     // LSTM bwd input proj
__device__ float g_x     [NROWS*DDIM];     // bi-LSTM hidden concat
__device__ float g_hout  [BB*DDIM];        // final LSTM states
__device__ float g_adj   [BB*ML*ML];       // min(adj1+adj2,1)
__device__ float g_denom [NROWS];          // row sums + 1e-7
__device__ float g_outs  [NROWS*DDIM];     // bert stream
__device__ float g_outp  [NROWS*DDIM];     // gcn stream
__device__ float g_qkv   [NROWS*3*DDIM];
__device__ float g_scores[BB*ML*ML];
__device__ float g_ctx   [NROWS*DDIM];
__device__ float g_buf   [NROWS*DDIM];
__device__ float g_abuf  [NROWS*DDIM];
__device__ float g_hmid  [NROWS*DDIM];

// ---------------- segment sum of bert tokens ----------------------------------
__global__ void seg_sum_tmps(const float* __restrict__ bert,
                             const int* __restrict__ tran_idx,
                             float* __restrict__ tmps)
{
    int r = blockIdx.x;            // b*ML + l
    int b = r / ML;
    int i0 = tran_idx[r*2 + 0];
    int i1 = tran_idx[r*2 + 1];
    long long ob = (long long)r * EMBD;
    for (int f = threadIdx.x; f < EMBD; f += blockDim.x) {
        float acc = 0.f;
        for (int s = i0; s < i1; s++)
            acc += bert[((long long)b*SS + 1 + s)*EMBD + f];
        tmps[ob + f] = acc;
    }
}

// ---------------- adjacency prep ----------------------------------------------
__global__ void adjprep(const float* __restrict__ a1, const float* __restrict__ a2,
                        float* __restrict__ adj, float* __restrict__ denom)
{
    int r = blockIdx.x;            // b*ML + i
    long long base = (long long)r * ML;
    int tid = threadIdx.x;         // 128
    float acc = 0.f;
    for (int jx = tid; jx < ML; jx += blockDim.x) {
        float v = fminf(a1[base+jx] + a2[base+jx], 1.f);
        adj[base+jx] = v;
        acc += v;
    }
    __shared__ float sh[128];
    sh[tid] = acc; __syncthreads();
    for (int s = 64; s > 0; s >>= 1) { if (tid < s) sh[tid] += sh[tid+s]; __syncthreads(); }
    if (tid == 0) denom[r] = sh[0] + 1e-7f;
}

// ---------------- generic tiled fp32 GEMM (NN / NT), optional bias+GELU -------
// 128x64 tile, 8x4 per thread, 256 threads. FFMA-bound (1.5 B smem / FMA).
// C[m,n] = sum_k A[m,k] * (transB ? B[n,k] : B[k,n])  (+bias[n]) (+gelu)
__global__ void __launch_bounds__(256)
gemm_kernel(const float* __restrict__ A, int lda, long long sA,
            const float* __restrict__ B, int ldb, long long sB,
            const float* __restrict__ bias,
            float* __restrict__ C, int ldc, long long sC,
            int M, int N, int K, int act, int transB)
{
    A += (long long)blockIdx.z * sA;
    B += (long long)blockIdx.z * sB;
    C += (long long)blockIdx.z * sC;
    __shared__ float As[16][132];   // [k][m] 128 rows of M
    __shared__ float Bs[16][68];    // [k][n] 64 cols of N
    const int row0 = blockIdx.y * 128, col0 = blockIdx.x * 64;
    const int tid = threadIdx.x;
    const int ty = tid >> 4, tx = tid & 15;   // ty: 16 row-groups of 8, tx: 16 col-groups of 4
    float acc[8][4] = {};
    for (int k0 = 0; k0 < K; k0 += 16) {
        // load A tile: 128x16 = 2048 elements, 8 per thread
        #pragma unroll
        for (int i = 0; i < 8; i++) {
            int idx = tid + i*256;
            int ar = idx >> 4, ac = idx & 15;
            int gr = row0 + ar, gc = k0 + ac;
            As[ac][ar] = (gr < M && gc < K) ? A[(long long)gr*lda + gc] : 0.f;
        }
        // load B tile: 64x16 = 1024 elements, 4 per thread
        if (transB) {
            #pragma unroll
            for (int i = 0; i < 4; i++) {
                int idx = tid + i*256;
                int nr = idx >> 4, nc = idx & 15;
                int gn = col0 + nr, gk = k0 + nc;
                Bs[nc][nr] = (gn < N && gk < K) ? B[(long long)gn*ldb + gk] : 0.f;
            }
        } else {
            #pragma unroll
            for (int i = 0; i < 4; i++) {
                int idx = tid + i*256;
                int br = idx >> 6, bc = idx & 63;
                int gr = k0 + br, gc = col0 + bc;
                Bs[br][bc] = (gr < K && gc < N) ? B[(long long)gr*ldb + gc] : 0.f;
            }
        }
        __syncthreads();
        #pragma unroll
        for (int kk = 0; kk < 16; kk++) {
            float4 a0 = *(const float4*)&As[kk][ty*8];
            float4 a1 = *(const float4*)&As[kk][ty*8 + 4];
            float4 b0 = *(const float4*)&Bs[kk][tx*4];
            float av[8] = {a0.x, a0.y, a0.z, a0.w, a1.x, a1.y, a1.z, a1.w};
            float bv[4] = {b0.x, b0.y, b0.z, b0.w};
            #pragma unroll
            for (int i = 0; i < 8; i++)
                #pragma unroll
                for (int j = 0; j < 4; j++)
                    acc[i][j] += av[i] * bv[j];
        }
        __syncthreads();
    }
    #pragma unroll
    for (int i = 0; i < 8; i++) {
        int gr = row0 + ty*8 + i;
        if (gr >= M) continue;
        #pragma unroll
        for (int j = 0; j < 4; j++) {
            int gc = col0 + tx*4 + j;
            if (gc >= N) continue;
            float v = acc[i][j] + (bias ? bias[gc] : 0.f);
            if (act == 1) v = 0.5f * v * (1.f + erff(v * 0.70710678118654752f));
            C[(long long)gr*ldc + gc] = v;
        }
    }
}

// ---------------- bidirectional LSTM recurrence -------------------------------
// grid (32, 2): blockIdx.x = batch, blockIdx.y = direction. 416 threads.
// Per thread j<400: Whh column j (100 floats) held in registers.
__global__ void __launch_bounds__(416, 1)
lstm_kernel(const float* __restrict__ xpf, const float* __restrict__ xpb,
            const float* __restrict__ Whh_f, const float* __restrict__ Whh_b,
            const int* __restrict__ tran_len,
            float* __restrict__ xout, float* __restrict__ hout)
{
    int b   = blockIdx.x;
    int dir = blockIdx.y;
    const float* xp  = dir ? xpb   : xpf;
    const float* Whh = dir ? Whh_b : Whh_f;
    int len = tran_len[b];
    int j = threadIdx.x;
    __shared__ __align__(16) float h_sh[104];
    __shared__ float gates[400];
    float w[100];
    if (j < 400) {
        #pragma unroll
        for (int k = 0; k < 100; k++) w[k] = Whh[k*400 + j];
    }
    if (j < 104) h_sh[j] = 0.f;
    float h_r = 0.f, c_r = 0.f;
    __syncthreads();
    for (int t = 0; t < 500; t++) {
        int p = dir ? (499 - t) : t;
        if (j < 400) {
            float a0 = 0.f, a1 = 0.f, a2 = 0.f, a3 = 0.f;
            #pragma unroll
            for (int k = 0; k < 100; k += 4) {
                float4 h4 = *(const float4*)&h_sh[k];
                a0 += h4.x * w[k];
                a1 += h4.y * w[k+1];
                a2 += h4.z * w[k+2];
                a3 += h4.w * w[k+3];
            }
            gates[j] = xp[((long long)(b*500 + p))*400 + j] + ((a0+a1)+(a2+a3));
        }
        __syncthreads();
        if (j < 100) {
            float ig = gates[j], fg = gates[100+j], cg = gates[200+j], og = gates[300+j];
            float si = 1.f/(1.f + expf(-ig));
            float sf = 1.f/(1.f + expf(-fg));
            float so = 1.f/(1.f + expf(-og));
            float cn = sf*c_r + si*tanhf(cg);
            float hn = so*tanhf(cn);
            float m = (p < len) ? 1.f : 0.f;
            h_r = m*hn + (1.f - m)*h_r;
            c_r = m*cn + (1.f - m)*c_r;
            h_sh[j] = h_r;
            xout[((long long)(b*500 + p))*200 + dir*100 + j] = h_r * m;
        }
        __syncthreads();
    }
    if (j < 100) hout[b*200 + dir*100 + j] = h_r;
}

// ---------------- row softmax with scale + additive mask ----------------------
__global__ void softmax_rows(float* __restrict__ S, const int* __restrict__ tran_len)
{
    int r = blockIdx.x;            // b*ML + q
    int b = r / ML;
    int len = tran_len[b];
    float* row = S + (long long)r * ML;
    int tid = threadIdx.x;         // 256
    const float scale = 0.070710678118654752f;   // 1/sqrt(200)
    int c0 = tid, c1 = tid + 256;
    float v0 = -1e30f, v1 = -1e30f;
    if (c0 < ML) v0 = row[c0]*scale + (c0 < len ? 0.f : -10000.f);
    if (c1 < ML) v1 = row[c1]*scale + (c1 < len ? 0.f : -10000.f);
    __shared__ float sh[256];
    sh[tid] = fmaxf(v0, v1); __syncthreads();
    for (int s = 128; s > 0; s >>= 1) { if (tid < s) sh[tid] = fmaxf(sh[tid], sh[tid+s]); __syncthreads(); }
    float mx = sh[0]; __syncthreads();
    float e0 = (c0 < ML) ? expf(v0 - mx) : 0.f;
    float e1 = (c1 < ML) ? expf(v1 - mx) : 0.f;
    sh[tid] = e0 + e1; __syncthreads();
    for (int s = 128; s > 0; s >>= 1) { if (tid < s) sh[tid] += sh[tid+s]; __syncthreads(); }
    float inv = 1.f / sh[0];
    if (c0 < ML) row[c0] = e0 * inv;
    if (c1 < ML) row[c1] = e1 * inv;
}

// ---------------- LayerNorm(X + R) * g + b ------------------------------------
__global__ void ln_residual(const float* __restrict__ X, const float* __restrict__ R,
                            const float* __restrict__ g, const float* __restrict__ bt,
                            float* __restrict__ out)
{
    int r = blockIdx.x;
    int tid = threadIdx.x;         // 256
    __shared__ float sh[256];
    __shared__ float stat[2];
    long long base = (long long)r * DDIM;
    float v = 0.f;
    if (tid < DDIM) v = X[base+tid] + R[base+tid];
    sh[tid] = (tid < DDIM) ? v : 0.f; __syncthreads();
    for (int s = 128; s > 0; s >>= 1) { if (tid < s) sh[tid] += sh[tid+s]; __syncthreads(); }
    if (tid == 0) stat[0] = sh[0] / DDIM; __syncthreads();
    float m = stat[0];
    float d = v - m;
    sh[tid] = (tid < DDIM) ? d*d : 0.f; __syncthreads();
    for (int s = 128; s > 0; s >>= 1) { if (tid < s) sh[tid] += sh[tid+s]; __syncthreads(); }
    if (tid == 0) stat[1] = sh[0] / DDIM; __syncthreads();
    if (tid < DDIM)
        out[base+tid] = d * rsqrtf(stat[1] + 1e-20f) * g[tid] + bt[tid];
}

// ---------------- GCN update: out += relu(buf / denom[row]) -------------------
__global__ void gcn_update(const float* __restrict__ buf, const float* __restrict__ denom,
                           float* __restrict__ outp)
{
    int i = blockIdx.x * blockDim.x + threadIdx.x;
    if (i < NROWS*DDIM) {
        int row = i / DDIM;
        float v = buf[i] / denom[row];
        outp[i] += fmaxf(v, 0.f);
    }
}

// ---------------- copy x into both streams ------------------------------------
__global__ void copy2(const float* __restrict__ src, float* __restrict__ d1,
                      float* __restrict__ d2, int n)
{
    int i = blockIdx.x * blockDim.x + threadIdx.x;
    if (i < n) { float v = src[i]; d1[i] = v; d2[i] = v; }
}

// ---------------- final feature + fc ------------------------------------------
__global__ void final_kernel(const float* __restrict__ outs, const float* __restrict__ outp,
                             const float* __restrict__ x, const float* __restrict__ hout,
                             const int* __restrict__ span_idx,
                             const float* __restrict__ fcW, const float* __restrict__ fcb,
                             float* __restrict__ out)
{
    int b = blockIdx.x;
    int tid = threadIdx.x;         // 256
    __shared__ float t0[200], t1[200];
    __shared__ float red[256];
    int s0 = span_idx[b*8 + 0];
    int s1 = span_idx[b*8 + 1];
    for (int d = tid; d < 200; d += 256) {
        float a0 = 0.f, a1 = 0.f;
        for (int s = s0; s < s1; s++) {
            long long idx = ((long long)(b*500 + s))*200 + d;
            a0 += outs[idx] + outp[idx];
            a1 += x[idx];
        }
        t0[d] = a0; t1[d] = a1;
    }
    __syncthreads();
    float p[3] = {0.f, 0.f, 0.f};
    for (int d = tid; d < 200; d += 256) {
        float f0 = hout[b*200 + d];
        float v0 = t0[d], v1 = t1[d];
        float fe[5] = {f0, v0, v1, v0*v1, fabsf(v0 - v1)};
        #pragma unroll
        for (int q = 0; q < 5; q++) {
            int fi = q*200 + d;
            p[0] += fe[q] * fcW[fi*3 + 0];
            p[1] += fe[q] * fcW[fi*3 + 1];
            p[2] += fe[q] * fcW[fi*3 + 2];
        }
    }
    for (int q = 0; q < 3; q++) {
        red[tid] = p[q]; __syncthreads();
        for (int s = 128; s > 0; s >>= 1) { if (tid < s) red[tid] += red[tid+s]; __syncthreads(); }
        if (tid == 0) out[b*3 + q] = red[0] + fcb[q];
        __syncthreads();
    }
}

// ---------------- launch sequence ---------------------------------------------
extern "C" void kernel_launch(void* const* d_in, const int* in_sizes, int n_in,
                              void* d_out, int out_size)
{
    (void)in_sizes; (void)n_in; (void)out_size;
    const float* bert  = (const float*)d_in[0];
    const float* adj1  = (const float*)d_in[1];
    const float* adj2  = (const float*)d_in[2];
    const float* Wih_f = (const float*)d_in[3];
    const float* Whh_f = (const float*)d_in[4];
    const float* b_f   = (const float*)d_in[5];
    const float* Wih_b = (const float*)d_in[6];
    const float* Whh_b = (const float*)d_in[7];
    const float* b_b   = (const float*)d_in[8];
    const float* gc_W  = (const float*)d_in[9];
    const float* Wqkv  = (const float*)d_in[10];
    const float* bqkv  = (const float*)d_in[11];
    const float* Wao   = (const float*)d_in[12];
    const float* bao   = (const float*)d_in[13];
    const float* ln1g  = (const float*)d_in[14];
    const float* ln1b  = (const float*)d_in[15];
    const float* Wi    = (const float*)d_in[16];
    const float* bi    = (const float*)d_in[17];
    const float* Wo    = (const float*)d_in[18];
    const float* bo    = (const float*)d_in[19];
    const float* ln2g  = (const float*)d_in[20];
    const float* ln2b  = (const float*)d_in[21];
    const float* fcW   = (const float*)d_in[22];
    const float* fcb   = (const float*)d_in[23];
    const int* tran_idx = (const int*)d_in[24];
    const int* tran_len = (const int*)d_in[25];
    const int* span_idx = (const int*)d_in[26];
    float* out = (float*)d_out;

    float *tmps, *xpf, *xpb, *xbuf, *houtb, *adjm, *denom, *outs, *outp;
    float *qkv, *scores, *ctx, *buf, *abuf, *hmid;
    cudaGetSymbolAddress((void**)&tmps,   g_tmps);
    cudaGetSymbolAddress((void**)&xpf,    g_xpf);
    cudaGetSymbolAddress((void**)&xpb,    g_xpb);
    cudaGetSymbolAddress((void**)&xbuf,   g_x);
    cudaGetSymbolAddress((void**)&houtb,  g_hout);
    cudaGetSymbolAddress((void**)&adjm,   g_adj);
    cudaGetSymbolAddress((void**)&denom,  g_denom);
    cudaGetSymbolAddress((void**)&outs,   g_outs);
    cudaGetSymbolAddress((void**)&outp,   g_outp);
    cudaGetSymbolAddress((void**)&qkv,    g_qkv);
    cudaGetSymbolAddress((void**)&scores, g_scores);
    cudaGetSymbolAddress((void**)&ctx,    g_ctx);
    cudaGetSymbolAddress((void**)&buf,    g_buf);
    cudaGetSymbolAddress((void**)&abuf,   g_abuf);
    cudaGetSymbolAddress((void**)&hmid,   g_hmid);

    seg_sum_tmps<<<NROWS, 256>>>(bert, tran_idx, tmps);
    adjprep<<<NROWS, 128>>>(adj1, adj2, adjm, denom);

    // LSTM input projections: tmps(16000x768) @ Wih(768x400) + b
    gemm_kernel<<<dim3(7, 125, 1), 256>>>(tmps, EMBD, 0, Wih_f, 400, 0, b_f,
                                          xpf, 400, 0, NROWS, 400, EMBD, 0, 0);
    gemm_kernel<<<dim3(7, 125, 1), 256>>>(tmps, EMBD, 0, Wih_b, 400, 0, b_b,
                                          xpb, 400, 0, NROWS, 400, EMBD, 0, 0);

    lstm_kernel<<<dim3(32, 2), 416>>>(xpf, xpb, Whh_f, Whh_b, tran_len, xbuf, houtb);
    copy2<<<(NROWS*DDIM + 255)/256, 256>>>(xbuf, outs, outp, NROWS*DDIM);

    for (int i = 0; i < 3; i++) {
        // QKV projection
        gemm_kernel<<<dim3(10, 125, 1), 256>>>(outs, DDIM, 0, Wqkv + (long long)i*DDIM*600, 600, 0,
                                               bqkv + i*600, qkv, 600, 0,
                                               NROWS, 600, DDIM, 0, 0);
        // scores = Q @ K^T (batched NT)
        gemm_kernel<<<dim3(8, 4, 32), 256>>>(qkv, 600, 300000LL, qkv + 200, 600, 300000LL,
                                             nullptr, scores, ML, 250000LL,
                                             ML, ML, DDIM, 0, 1);
        softmax_rows<<<NROWS, 256>>>(scores, tran_len);
        // ctx = P @ V (batched NN)
        gemm_kernel<<<dim3(4, 4, 32), 256>>>(scores, ML, 250000LL, qkv + 400, 600, 300000LL,
                                             nullptr, ctx, DDIM, 100000LL,
                                             ML, DDIM, ML, 0, 0);
        // attention out projection + LN residual
        gemm_kernel<<<dim3(4, 125, 1), 256>>>(ctx, DDIM, 0, Wao + (long long)i*DDIM*DDIM, DDIM, 0,
                                              bao + i*DDIM, buf, DDIM, 0,
                                              NROWS, DDIM, DDIM, 0, 0);
        ln_residual<<<NROWS, 256>>>(buf, outs, ln1g + i*DDIM, ln1b + i*DDIM, abuf);
        // FFN
        gemm_kernel<<<dim3(4, 125, 1), 256>>>(abuf, DDIM, 0, Wi + (long long)i*DDIM*DDIM, DDIM, 0,
                                              bi + i*DDIM, hmid, DDIM, 0,
                                              NROWS, DDIM, DDIM, 1, 0);
        gemm_kernel<<<dim3(4, 125, 1), 256>>>(hmid, DDIM, 0, Wo + (long long)i*DDIM*DDIM, DDIM, 0,
                                              bo + i*DDIM, buf, DDIM, 0,
                                              NROWS, DDIM, DDIM, 0, 0);
        ln_residual<<<NROWS, 256>>>(buf, abuf, ln2g + i*DDIM, ln2b + i*DDIM, outs);
        // GCN stream (uses previous-iteration outp)
        gemm_kernel<<<dim3(4, 125, 1), 256>>>(outp, DDIM, 0, gc_W, DDIM, 0, nullptr,
                                              ctx, DDIM, 0, NROWS, DDIM, DDIM, 0, 0);
        gemm_kernel<<<dim3(4, 4, 32), 256>>>(adjm, ML, 250000LL, ctx, DDIM, 100000LL,
                                             nullptr, buf, DDIM, 100000LL,
                                             ML, DDIM, ML, 0, 0);
        gcn_update<<<(NROWS*DDIM + 255)/256, 256>>>(buf, denom, outp);
    }

    final_kernel<<<32, 256>>>(outs, outp, xbuf, houtb, span_idx, fcW, fcb, out);
}

// round 7
// speedup vs baseline: 1.2016x; 1.2016x over previous
#include <cuda_runtime.h>
#include <math.h>

// Problem constants
#define BB   32
#define SS   1024
#define ML   500
#define HH   100
#define DDIM 200
#define EMBD 768
#define NROWS (BB*ML)   // 16000

// ---------------- scratch (device globals; no runtime allocation) -------------
__device__ float g_tmps  [NROWS*EMBD];     // seg-summed tokens
__device__ float g_xpf   [NROWS*4*HH];     // LSTM fwd input proj
__device__ float g_xpb   [NROWS*4*HH];     // LSTM bwd input proj
__device__ float g_x     [NROWS*DDIM];     // bi-LSTM hidden concat
__device__ float g_hout  [BB*DDIM];        // final LSTM states
__device__ float g_adj   [BB*ML*ML];       // min(adj1+adj2,1)
__device__ float g_denom [NROWS];          // row sums + 1e-7
__device__ float g_outs  [NROWS*DDIM];     // bert stream
__device__ float g_outp  [NROWS*DDIM];     // gcn stream
__device__ float g_qkv   [NROWS*3*DDIM];
__device__ float g_scores[BB*ML*ML];
__device__ float g_ctx   [NROWS*DDIM];
__device__ float g_buf   [NROWS*DDIM];
__device__ float g_abuf  [NROWS*DDIM];
__device__ float g_hmid  [NROWS*DDIM];

// ---------------- f32x2 packed helpers (sm_100+; FFMA2 in SASS) ---------------
__device__ __forceinline__ unsigned long long pk2(float lo, float hi) {
    unsigned long long r;
    asm("mov.b64 %0, {%1, %2};" : "=l"(r) : "r"(__float_as_uint(lo)), "r"(__float_as_uint(hi)));
    return r;
}
__device__ __forceinline__ unsigned long long dup2(float v) {
    unsigned long long r;
    unsigned int u = __float_as_uint(v);
    asm("mov.b64 %0, {%1, %1};" : "=l"(r) : "r"(u));
    return r;
}
__device__ __forceinline__ void fma2(unsigned long long &d, unsigned long long a, unsigned long long b) {
    asm("fma.rn.f32x2 %0, %1, %2, %3;" : "=l"(d) : "l"(a), "l"(b), "l"(d));
}
__device__ __forceinline__ void upk2(unsigned long long v, float &lo, float &hi) {
    unsigned int a, b;
    asm("mov.b64 {%0, %1}, %2;" : "=r"(a), "=r"(b) : "l"(v));
    lo = __uint_as_float(a); hi = __uint_as_float(b);
}

// ---------------- segment sum of bert tokens ----------------------------------
__global__ void seg_sum_tmps(const float* __restrict__ bert,
                             const int* __restrict__ tran_idx,
                             float* __restrict__ tmps)
{
    int r = blockIdx.x;            // b*ML + l
    int b = r / ML;
    int i0 = tran_idx[r*2 + 0];
    int i1 = tran_idx[r*2 + 1];
    long long ob = (long long)r * EMBD;
    for (int f = threadIdx.x; f < EMBD; f += blockDim.x) {
        float acc = 0.f;
        for (int s = i0; s < i1; s++)
            acc += bert[((long long)b*SS + 1 + s)*EMBD + f];
        tmps[ob + f] = acc;
    }
}

// ---------------- adjacency prep ----------------------------------------------
__global__ void adjprep(const float* __restrict__ a1, const float* __restrict__ a2,
                        float* __restrict__ adj, float* __restrict__ denom)
{
    int r = blockIdx.x;            // b*ML + i
    long long base = (long long)r * ML;
    int tid = threadIdx.x;         // 128
    float acc = 0.f;
    for (int jx = tid; jx < ML; jx += blockDim.x) {
        float v = fminf(a1[base+jx] + a2[base+jx], 1.f);
        adj[base+jx] = v;
        acc += v;
    }
    __shared__ float sh[128];
    sh[tid] = acc; __syncthreads();
    for (int s = 64; s > 0; s >>= 1) { if (tid < s) sh[tid] += sh[tid+s]; __syncthreads(); }
    if (tid == 0) denom[r] = sh[0] + 1e-7f;
}

// ---------------- generic tiled fp32 GEMM (NN / NT) with FFMA2 ----------------
// 128x128 tile, 8x8 per thread, 256 threads, f32x2 packed accumulate.
// C[m,n] = sum_k A[m,k] * (transB ? B[n,k] : B[k,n])  (+bias[n]) (+gelu)
__global__ void __launch_bounds__(256)
gemm_kernel(const float* __restrict__ A, int lda, long long sA,
            const float* __restrict__ B, int ldb, long long sB,
            const float* __restrict__ bias,
            float* __restrict__ C, int ldc, long long sC,
            int M, int N, int K, int act, int transB)
{
    A += (long long)blockIdx.z * sA;
    B += (long long)blockIdx.z * sB;
    C += (long long)blockIdx.z * sC;
    __shared__ float As[16][132];   // [k][m] 128 rows of M
    __shared__ float Bs[16][132];   // [k][n] 128 cols of N
    const int row0 = blockIdx.y * 128, col0 = blockIdx.x * 128;
    const int tid = threadIdx.x;
    const int ty = tid >> 4, tx = tid & 15;   // 16x16 thread grid; 8 rows x 8 cols each
    // acc[rp][c]: packed rows {row0+ty*8+2rp, +1}, col col0+tx*8+c
    unsigned long long acc[4][8];
    #pragma unroll
    for (int i = 0; i < 4; i++)
        #pragma unroll
        for (int j = 0; j < 8; j++) acc[i][j] = 0ULL;

    for (int k0 = 0; k0 < K; k0 += 16) {
        // load A tile: 128(M)x16(K), 8 elements per thread
        #pragma unroll
        for (int i = 0; i < 8; i++) {
            int idx = tid + i*256;
            int ar = idx >> 4, ac = idx & 15;
            int gr = row0 + ar, gc = k0 + ac;
            As[ac][ar] = (gr < M && gc < K) ? A[(long long)gr*lda + gc] : 0.f;
        }
        // load B tile: 16(K)x128(N), 8 elements per thread
        if (transB) {
            #pragma unroll
            for (int i = 0; i < 8; i++) {
                int idx = tid + i*256;
                int nr = idx >> 4, nc = idx & 15;     // nr: N index, nc: K index
                int gn = col0 + nr, gk = k0 + nc;
                Bs[nc][nr] = (gn < N && gk < K) ? B[(long long)gn*ldb + gk] : 0.f;
            }
        } else {
            #pragma unroll
            for (int i = 0; i < 8; i++) {
                int idx = tid + i*256;
                int br = idx >> 7, bc = idx & 127;    // br: K index, bc: N index
                int gr = k0 + br, gc = col0 + bc;
                Bs[br][bc] = (gr < K && gc < N) ? B[(long long)gr*ldb + gc] : 0.f;
            }
        }
        __syncthreads();
        #pragma unroll
        for (int kk = 0; kk < 16; kk++) {
            float4 a0 = *(const float4*)&As[kk][ty*8];
            float4 a1 = *(const float4*)&As[kk][ty*8 + 4];
            float4 b0 = *(const float4*)&Bs[kk][tx*8];
            float4 b1 = *(const float4*)&Bs[kk][tx*8 + 4];
            unsigned long long ap[4] = { pk2(a0.x, a0.y), pk2(a0.z, a0.w),
                                         pk2(a1.x, a1.y), pk2(a1.z, a1.w) };
            unsigned long long bd[8] = { dup2(b0.x), dup2(b0.y), dup2(b0.z), dup2(b0.w),
                                         dup2(b1.x), dup2(b1.y), dup2(b1.z), dup2(b1.w) };
            #pragma unroll
            for (int rp = 0; rp < 4; rp++)
                #pragma unroll
                for (int c = 0; c < 8; c++)
                    fma2(acc[rp][c], ap[rp], bd[c]);
        }
        __syncthreads();
    }
    #pragma unroll
    for (int rp = 0; rp < 4; rp++) {
        int gr0 = row0 + ty*8 + rp*2;
        #pragma unroll
        for (int c = 0; c < 8; c++) {
            int gc = col0 + tx*8 + c;
            if (gc >= N) continue;
            float lo, hi;
            upk2(acc[rp][c], lo, hi);
            float bz = bias ? bias[gc] : 0.f;
            if (gr0 < M) {
                float v = lo + bz;
                if (act == 1) v = 0.5f * v * (1.f + erff(v * 0.70710678118654752f));
                C[(long long)gr0*ldc + gc] = v;
            }
            if (gr0 + 1 < M) {
                float v = hi + bz;
                if (act == 1) v = 0.5f * v * (1.f + erff(v * 0.70710678118654752f));
                C[(long long)(gr0+1)*ldc + gc] = v;
            }
        }
    }
}

// ---------------- bidirectional LSTM recurrence -------------------------------
// grid (32, 2): blockIdx.x = batch, blockIdx.y = direction. 416 threads.
// Per thread j<400: Whh column j (100 floats) held in registers.
__global__ void __launch_bounds__(416, 1)
lstm_kernel(const float* __restrict__ xpf, const float* __restrict__ xpb,
            const float* __restrict__ Whh_f, const float* __restrict__ Whh_b,
            const int* __restrict__ tran_len,
            float* __restrict__ xout, float* __restrict__ hout)
{
    int b   = blockIdx.x;
    int dir = blockIdx.y;
    const float* xp  = dir ? xpb   : xpf;
    const float* Whh = dir ? Whh_b : Whh_f;
    int len = tran_len[b];
    int j = threadIdx.x;
    __shared__ __align__(16) float h_sh[104];
    __shared__ float gates[400];
    float w[100];
    if (j < 400) {
        #pragma unroll
        for (int k = 0; k < 100; k++) w[k] = Whh[k*400 + j];
    }
    if (j < 104) h_sh[j] = 0.f;
    float h_r = 0.f, c_r = 0.f;
    __syncthreads();
    for (int t = 0; t < 500; t++) {
        int p = dir ? (499 - t) : t;
        if (j < 400) {
            float a0 = 0.f, a1 = 0.f, a2 = 0.f, a3 = 0.f;
            #pragma unroll
            for (int k = 0; k < 100; k += 4) {
                float4 h4 = *(const float4*)&h_sh[k];
                a0 += h4.x * w[k];
                a1 += h4.y * w[k+1];
                a2 += h4.z * w[k+2];
                a3 += h4.w * w[k+3];
            }
            gates[j] = xp[((long long)(b*500 + p))*400 + j] + ((a0+a1)+(a2+a3));
        }
        __syncthreads();
        if (j < 100) {
            float ig = gates[j], fg = gates[100+j], cg = gates[200+j], og = gates[300+j];
            float si = 1.f/(1.f + expf(-ig));
            float sf = 1.f/(1.f + expf(-fg));
            float so = 1.f/(1.f + expf(-og));
            float cn = sf*c_r + si*tanhf(cg);
            float hn = so*tanhf(cn);
            float m = (p < len) ? 1.f : 0.f;
            h_r = m*hn + (1.f - m)*h_r;
            c_r = m*cn + (1.f - m)*c_r;
            h_sh[j] = h_r;
            xout[((long long)(b*500 + p))*200 + dir*100 + j] = h_r * m;
        }
        __syncthreads();
    }
    if (j < 100) hout[b*200 + dir*100 + j] = h_r;
}

// ---------------- row softmax with scale + additive mask ----------------------
__global__ void softmax_rows(float* __restrict__ S, const int* __restrict__ tran_len)
{
    int r = blockIdx.x;            // b*ML + q
    int b = r / ML;
    int len = tran_len[b];
    float* row = S + (long long)r * ML;
    int tid = threadIdx.x;         // 256
    const float scale = 0.070710678118654752f;   // 1/sqrt(200)
    int c0 = tid, c1 = tid + 256;
    float v0 = -1e30f, v1 = -1e30f;
    if (c0 < ML) v0 = row[c0]*scale + (c0 < len ? 0.f : -10000.f);
    if (c1 < ML) v1 = row[c1]*scale + (c1 < len ? 0.f : -10000.f);
    __shared__ float sh[256];
    sh[tid] = fmaxf(v0, v1); __syncthreads();
    for (int s = 128; s > 0; s >>= 1) { if (tid < s) sh[tid] = fmaxf(sh[tid], sh[tid+s]); __syncthreads(); }
    float mx = sh[0]; __syncthreads();
    float e0 = (c0 < ML) ? expf(v0 - mx) : 0.f;
    float e1 = (c1 < ML) ? expf(v1 - mx) : 0.f;
    sh[tid] = e0 + e1; __syncthreads();
    for (int s = 128; s > 0; s >>= 1) { if (tid < s) sh[tid] += sh[tid+s]; __syncthreads(); }
    float inv = 1.f / sh[0];
    if (c0 < ML) row[c0] = e0 * inv;
    if (c1 < ML) row[c1] = e1 * inv;
}

// ---------------- LayerNorm(X + R) * g + b ------------------------------------
__global__ void ln_residual(const float* __restrict__ X, const float* __restrict__ R,
                            const float* __restrict__ g, const float* __restrict__ bt,
                            float* __restrict__ out)
{
    int r = blockIdx.x;
    int tid = threadIdx.x;         // 256
    __shared__ float sh[256];
    __shared__ float stat[2];
    long long base = (long long)r * DDIM;
    float v = 0.f;
    if (tid < DDIM) v = X[base+tid] + R[base+tid];
    sh[tid] = (tid < DDIM) ? v : 0.f; __syncthreads();
    for (int s = 128; s > 0; s >>= 1) { if (tid < s) sh[tid] += sh[tid+s]; __syncthreads(); }
    if (tid == 0) stat[0] = sh[0] / DDIM; __syncthreads();
    float m = stat[0];
    float d = v - m;
    sh[tid] = (tid < DDIM) ? d*d : 0.f; __syncthreads();
    for (int s = 128; s > 0; s >>= 1) { if (tid < s) sh[tid] += sh[tid+s]; __syncthreads(); }
    if (tid == 0) stat[1] = sh[0] / DDIM; __syncthreads();
    if (tid < DDIM)
        out[base+tid] = d * rsqrtf(stat[1] + 1e-20f) * g[tid] + bt[tid];
}

// ---------------- GCN update: out += relu(buf / denom[row]) -------------------
__global__ void gcn_update(const float* __restrict__ buf, const float* __restrict__ denom,
                           float* __restrict__ outp)
{
    int i = blockIdx.x * blockDim.x + threadIdx.x;
    if (i < NROWS*DDIM) {
        int row = i / DDIM;
        float v = buf[i] / denom[row];
        outp[i] += fmaxf(v, 0.f);
    }
}

// ---------------- copy x into both streams ------------------------------------
__global__ void copy2(const float* __restrict__ src, float* __restrict__ d1,
                      float* __restrict__ d2, int n)
{
    int i = blockIdx.x * blockDim.x + threadIdx.x;
    if (i < n) { float v = src[i]; d1[i] = v; d2[i] = v; }
}

// ---------------- final feature + fc ------------------------------------------
__global__ void final_kernel(const float* __restrict__ outs, const float* __restrict__ outp,
                             const float* __restrict__ x, const float* __restrict__ hout,
                             const int* __restrict__ span_idx,
                             const float* __restrict__ fcW, const float* __restrict__ fcb,
                             float* __restrict__ out)
{
    int b = blockIdx.x;
    int tid = threadIdx.x;         // 256
    __shared__ float t0[200], t1[200];
    __shared__ float red[256];
    int s0 = span_idx[b*8 + 0];
    int s1 = span_idx[b*8 + 1];
    for (int d = tid; d < 200; d += 256) {
        float a0 = 0.f, a1 = 0.f;
        for (int s = s0; s < s1; s++) {
            long long idx = ((long long)(b*500 + s))*200 + d;
            a0 += outs[idx] + outp[idx];
            a1 += x[idx];
        }
        t0[d] = a0; t1[d] = a1;
    }
    __syncthreads();
    float p[3] = {0.f, 0.f, 0.f};
    for (int d = tid; d < 200; d += 256) {
        float f0 = hout[b*200 + d];
        float v0 = t0[d], v1 = t1[d];
        float fe[5] = {f0, v0, v1, v0*v1, fabsf(v0 - v1)};
        #pragma unroll
        for (int q = 0; q < 5; q++) {
            int fi = q*200 + d;
            p[0] += fe[q] * fcW[fi*3 + 0];
            p[1] += fe[q] * fcW[fi*3 + 1];
            p[2] += fe[q] * fcW[fi*3 + 2];
        }
    }
    for (int q = 0; q < 3; q++) {
        red[tid] = p[q]; __syncthreads();
        for (int s = 128; s > 0; s >>= 1) { if (tid < s) red[tid] += red[tid+s]; __syncthreads(); }
        if (tid == 0) out[b*3 + q] = red[0] + fcb[q];
        __syncthreads();
    }
}

// ---------------- launch sequence ---------------------------------------------
extern "C" void kernel_launch(void* const* d_in, const int* in_sizes, int n_in,
                              void* d_out, int out_size)
{
    (void)in_sizes; (void)n_in; (void)out_size;
    const float* bert  = (const float*)d_in[0];
    const float* adj1  = (const float*)d_in[1];
    const float* adj2  = (const float*)d_in[2];
    const float* Wih_f = (const float*)d_in[3];
    const float* Whh_f = (const float*)d_in[4];
    const float* b_f   = (const float*)d_in[5];
    const float* Wih_b = (const float*)d_in[6];
    const float* Whh_b = (const float*)d_in[7];
    const float* b_b   = (const float*)d_in[8];
    const float* gc_W  = (const float*)d_in[9];
    const float* Wqkv  = (const float*)d_in[10];
    const float* bqkv  = (const float*)d_in[11];
    const float* Wao   = (const float*)d_in[12];
    const float* bao   = (const float*)d_in[13];
    const float* ln1g  = (const float*)d_in[14];
    const float* ln1b  = (const float*)d_in[15];
    const float* Wi    = (const float*)d_in[16];
    const float* bi    = (const float*)d_in[17];
    const float* Wo    = (const float*)d_in[18];
    const float* bo    = (const float*)d_in[19];
    const float* ln2g  = (const float*)d_in[20];
    const float* ln2b  = (const float*)d_in[21];
    const float* fcW   = (const float*)d_in[22];
    const float* fcb   = (const float*)d_in[23];
    const int* tran_idx = (const int*)d_in[24];
    const int* tran_len = (const int*)d_in[25];
    const int* span_idx = (const int*)d_in[26];
    float* out = (float*)d_out;

    float *tmps, *xpf, *xpb, *xbuf, *houtb, *adjm, *denom, *outs, *outp;
    float *qkv, *scores, *ctx, *buf, *abuf, *hmid;
    cudaGetSymbolAddress((void**)&tmps,   g_tmps);
    cudaGetSymbolAddress((void**)&xpf,    g_xpf);
    cudaGetSymbolAddress((void**)&xpb,    g_xpb);
    cudaGetSymbolAddress((void**)&xbuf,   g_x);
    cudaGetSymbolAddress((void**)&houtb,  g_hout);
    cudaGetSymbolAddress((void**)&adjm,   g_adj);
    cudaGetSymbolAddress((void**)&denom,  g_denom);
    cudaGetSymbolAddress((void**)&outs,   g_outs);
    cudaGetSymbolAddress((void**)&outp,   g_outp);
    cudaGetSymbolAddress((void**)&qkv,    g_qkv);
    cudaGetSymbolAddress((void**)&scores, g_scores);
    cudaGetSymbolAddress((void**)&ctx,    g_ctx);
    cudaGetSymbolAddress((void**)&buf,    g_buf);
    cudaGetSymbolAddress((void**)&abuf,   g_abuf);
    cudaGetSymbolAddress((void**)&hmid,   g_hmid);

    seg_sum_tmps<<<NROWS, 256>>>(bert, tran_idx, tmps);
    adjprep<<<NROWS, 128>>>(adj1, adj2, adjm, denom);

    // LSTM input projections: tmps(16000x768) @ Wih(768x400) + b
    gemm_kernel<<<dim3(4, 125, 1), 256>>>(tmps, EMBD, 0, Wih_f, 400, 0, b_f,
                                          xpf, 400, 0, NROWS, 400, EMBD, 0, 0);
    gemm_kernel<<<dim3(4, 125, 1), 256>>>(tmps, EMBD, 0, Wih_b, 400, 0, b_b,
                                          xpb, 400, 0, NROWS, 400, EMBD, 0, 0);

    lstm_kernel<<<dim3(32, 2), 416>>>(xpf, xpb, Whh_f, Whh_b, tran_len, xbuf, houtb);
    copy2<<<(NROWS*DDIM + 255)/256, 256>>>(xbuf, outs, outp, NROWS*DDIM);

    for (int i = 0; i < 3; i++) {
        // QKV projection
        gemm_kernel<<<dim3(5, 125, 1), 256>>>(outs, DDIM, 0, Wqkv + (long long)i*DDIM*600, 600, 0,
                                              bqkv + i*600, qkv, 600, 0,
                                              NROWS, 600, DDIM, 0, 0);
        // scores = Q @ K^T (batched NT)
        gemm_kernel<<<dim3(4, 4, 32), 256>>>(qkv, 600, 300000LL, qkv + 200, 600, 300000LL,
                                             nullptr, scores, ML, 250000LL,
                                             ML, ML, DDIM, 0, 1);
        softmax_rows<<<NROWS, 256>>>(scores, tran_len);
        // ctx = P @ V (batched NN)
        gemm_kernel<<<dim3(2, 4, 32), 256>>>(scores, ML, 250000LL, qkv + 400, 600, 300000LL,
                                             nullptr, ctx, DDIM, 100000LL,
                                             ML, DDIM, ML, 0, 0);
        // attention out projection + LN residual
        gemm_kernel<<<dim3(2, 125, 1), 256>>>(ctx, DDIM, 0, Wao + (long long)i*DDIM*DDIM, DDIM, 0,
                                              bao + i*DDIM, buf, DDIM, 0,
                                              NROWS, DDIM, DDIM, 0, 0);
        ln_residual<<<NROWS, 256>>>(buf, outs, ln1g + i*DDIM, ln1b + i*DDIM, abuf);
        // FFN
        gemm_kernel<<<dim3(2, 125, 1), 256>>>(abuf, DDIM, 0, Wi + (long long)i*DDIM*DDIM, DDIM, 0,
                                              bi + i*DDIM, hmid, DDIM, 0,
                                              NROWS, DDIM, DDIM, 1, 0);
        gemm_kernel<<<dim3(2, 125, 1), 256>>>(hmid, DDIM, 0, Wo + (long long)i*DDIM*DDIM, DDIM, 0,
                                              bo + i*DDIM, buf, DDIM, 0,
                                              NROWS, DDIM, DDIM, 0, 0);
        ln_residual<<<NROWS, 256>>>(buf, abuf, ln2g + i*DDIM, ln2b + i*DDIM, outs);
        // GCN stream (uses previous-iteration outp)
        gemm_kernel<<<dim3(2, 125, 1), 256>>>(outp, DDIM, 0, gc_W, DDIM, 0, nullptr,
                                              ctx, DDIM, 0, NROWS, DDIM, DDIM, 0, 0);
        gemm_kernel<<<dim3(2, 4, 32), 256>>>(adjm, ML, 250000LL, ctx, DDIM, 100000LL,
                                             nullptr, buf, DDIM, 100000LL,
                                             ML, DDIM, ML, 0, 0);
        gcn_update<<<(NROWS*DDIM + 255)/256, 256>>>(buf, denom, outp);
    }

    final_kernel<<<32, 256>>>(outs, outp, xbuf, houtb, span_idx, fcW, fcb, out);
}